// round 4
// baseline (speedup 1.0000x reference)
#include <cuda_runtime.h>
#include <stdint.h>

#define HOPS 3
#define LBL  10
#define DIM  128
#define WARPS_PER_BLOCK 8
#define THREADS (WARPS_PER_BLOCK * 32)
#define UNROLL 4

// Scratch (no allocations allowed): per-(hop,label,dim) sums + per-label counts.
__device__ float g_sums[HOPS * LBL * DIM];
__device__ float g_counts[LBL];
__device__ int   g_is64;

// ---------------------------------------------------------------------------
// Kernel 0: zero scratch, assume int64 labels until detection says otherwise.
// ---------------------------------------------------------------------------
__global__ void zero_scratch_kernel() {
    int i = blockIdx.x * blockDim.x + threadIdx.x;
    if (i < HOPS * LBL * DIM) g_sums[i] = 0.0f;
    if (i < LBL) g_counts[i] = 0.0f;
    if (i == 0) g_is64 = 1;
}

// ---------------------------------------------------------------------------
// Kernel 1: labels dtype detection. If labels are int64 (values 0..9,
// little-endian), every odd 32-bit word is 0. If int32, odd words are random
// labels 0..9 and some are nonzero with overwhelming probability.
// Reads only N 32-bit words, which is in-bounds for both dtypes.
// ---------------------------------------------------------------------------
__global__ void detect_labels_kernel(const int* __restrict__ l32, int half_n) {
    int i = blockIdx.x * blockDim.x + threadIdx.x;
    if (i < half_n) {
        if (l32[2 * i + 1] != 0) g_is64 = 0;
    }
}

// ---------------------------------------------------------------------------
// Kernel 2: accumulate per-(hop,label) sums. One warp processes whole nodes
// (all 32 lanes on the same node => label is warp-uniform => conflict-free
// smem RMW). Per-warp private smem bank avoids inter-warp atomics in the hot
// loop. blockIdx.y = hop.
// ---------------------------------------------------------------------------
__global__ void __launch_bounds__(THREADS)
accumulate_kernel(const float* __restrict__ emb,
                  const void*  __restrict__ labels_raw,
                  int N) {
    __shared__ __align__(16) float acc[WARPS_PER_BLOCK * LBL * DIM]; // 40 KB
    __shared__ int scnt[LBL];

    const int tid  = threadIdx.x;
    const int warp = tid >> 5;
    const int lane = tid & 31;
    const int hop  = blockIdx.y;

    for (int i = tid; i < WARPS_PER_BLOCK * LBL * DIM; i += THREADS) acc[i] = 0.0f;
    if (tid < LBL) scnt[tid] = 0;
    const int is64 = g_is64;
    __syncthreads();

    const float4*    e4  = reinterpret_cast<const float4*>(emb) + (size_t)hop * N * (DIM / 4);
    const int*       l32 = reinterpret_cast<const int*>(labels_raw);
    const long long* l64 = reinterpret_cast<const long long*>(labels_raw);

    float* my = acc + warp * LBL * DIM;

    const int gw = blockIdx.x * WARPS_PER_BLOCK + warp;   // global warp id
    const int nw = gridDim.x * WARPS_PER_BLOCK;           // total warps (this hop)

    for (int base = gw * UNROLL; base < N; base += nw * UNROLL) {
        int    lab[UNROLL];
        float4 v[UNROLL];
#pragma unroll
        for (int k = 0; k < UNROLL; k++) {
            int n = base + k;
            if (n < N) {
                lab[k] = is64 ? (int)l64[n] : l32[n];
                v[k]   = e4[(size_t)n * (DIM / 4) + lane];
            } else {
                lab[k] = -1;
            }
        }
#pragma unroll
        for (int k = 0; k < UNROLL; k++) {
            if (lab[k] >= 0) {
                float4* p = reinterpret_cast<float4*>(my + lab[k] * DIM + lane * 4);
                float4 cur = *p;
                cur.x += v[k].x; cur.y += v[k].y; cur.z += v[k].z; cur.w += v[k].w;
                *p = cur;
                if (hop == 0 && lane == 0) atomicAdd(&scnt[lab[k]], 1);
            }
        }
    }
    __syncthreads();

    // Reduce the 8 warp banks, one global atomicAdd per (label,dim) per block.
    for (int i = tid; i < LBL * DIM; i += THREADS) {
        float s = 0.0f;
#pragma unroll
        for (int w = 0; w < WARPS_PER_BLOCK; w++) s += acc[w * LBL * DIM + i];
        atomicAdd(&g_sums[hop * LBL * DIM + i], s);
    }
    if (hop == 0 && tid < LBL && scnt[tid] != 0)
        atomicAdd(&g_counts[tid], (float)scnt[tid]);
}

// ---------------------------------------------------------------------------
// Kernel 3: finalize — centers = sums / max(count,1) + weight, then counts.
// Output layout: [HOPS*LBL*DIM centers][LBL counts] = 3850 floats.
// ---------------------------------------------------------------------------
__global__ void finalize_kernel(const float* __restrict__ weight, float* __restrict__ out) {
    int i = blockIdx.x * blockDim.x + threadIdx.x;
    if (i < HOPS * LBL * DIM) {
        int l = (i / DIM) % LBL;
        float c = g_counts[l];
        if (c < 1.0f) c = 1.0f;
        out[i] = g_sums[i] / c + weight[i];
    } else if (i < HOPS * LBL * DIM + LBL) {
        out[i] = g_counts[i - HOPS * LBL * DIM];
    }
}

// ---------------------------------------------------------------------------
extern "C" void kernel_launch(void* const* d_in, const int* in_sizes, int n_in,
                              void* d_out, int out_size) {
    const float* emb     = (const float*)d_in[0];   // [3, N, 128] f32
    const void*  labels  = d_in[1];                 // [N] int32 or int64
    const float* weight  = (const float*)d_in[2];   // [3, 10, 128] f32
    float*       out     = (float*)d_out;

    const int N = in_sizes[1];                      // element count of labels

    // 0) zero scratch
    zero_scratch_kernel<<<(HOPS * LBL * DIM + 255) / 256, 256>>>();

    // 1) detect labels dtype
    const int half_n = N / 2;
    detect_labels_kernel<<<(half_n + 1023) / 1024, 1024>>>((const int*)labels, half_n);

    // 2) accumulate: grid.x tuned for one full wave (5 blocks/SM @ 40KB smem,
    //    148 SMs -> 740 resident; 240*3 = 720 blocks)
    dim3 grid(240, HOPS, 1);
    accumulate_kernel<<<grid, THREADS>>>(emb, labels, N);

    // 3) finalize
    const int total = HOPS * LBL * DIM + LBL;
    finalize_kernel<<<(total + 255) / 256, 256>>>(weight, out);
}